// round 1
// baseline (speedup 1.0000x reference)
#include <cuda_runtime.h>
#include <math.h>

#define BATCH 4
#define SEQ 2048
#define DMODEL 1024
#define NH 16
#define DHEAD 64
#define PSZ (BATCH*NH*SEQ*DHEAD)   /* 8,388,608 elements per projection */

// Scratch (no cudaMalloc allowed): q,k,v | attention output | repacked W | repacked bias
__device__ float g_qkv[3*PSZ];                 // [proj][b][h][s][e]
__device__ float g_z[BATCH*SEQ*DMODEL];        // [b][s][h*64+e]
__device__ float g_w[3*DMODEL*DMODEL];         // [k][3072]  (q|k|v columns)
__device__ float g_bias[3*DMODEL];

// ---------------------------------------------------------------------------
// Repack Wq/Wk/Wv [H,D,DH] -> g_w [K=1024][N=3072], biases -> g_bias[3072]
// ---------------------------------------------------------------------------
__global__ void repack_w_kernel(const float* __restrict__ Wq,
                                const float* __restrict__ Wk,
                                const float* __restrict__ Wv,
                                const float* __restrict__ bq,
                                const float* __restrict__ bk,
                                const float* __restrict__ bv) {
    int idx = blockIdx.x * 256 + threadIdx.x;
    if (idx < 3*DMODEL*DMODEL) {
        int k = idx / 3072;
        int c = idx % 3072;
        int proj = c >> 10;
        int rem  = c & 1023;
        int h = rem >> 6, e = rem & 63;
        const float* W = (proj == 0) ? Wq : (proj == 1 ? Wk : Wv);
        g_w[idx] = W[((size_t)h*DMODEL + k)*DHEAD + e];
    }
    if (idx < 3*DMODEL) {
        int proj = idx >> 10, rem = idx & 1023;
        const float* bb = (proj == 0) ? bq : (proj == 1 ? bk : bv);
        g_bias[idx] = bb[rem];
    }
}

// ---------------------------------------------------------------------------
// SGEMM: C[8192, NN] = A[8192,1024] * B[1024, NN] + bias
// 128x128 block tile, BK=8, 256 threads, 8x8 microtile, reg prefetch.
// MODE 0: A=x (param), B=g_w, bias=g_bias, scatter to g_qkv.
// MODE 1: A=g_z, B=Wo (param), bias=bo (param), write Cout (d_out).
// ---------------------------------------------------------------------------
template<int NN, int MODE>
__global__ __launch_bounds__(256)
void sgemm_kernel(const float* __restrict__ A_ext,
                  const float* __restrict__ B_ext,
                  const float* __restrict__ bias_ext,
                  float* __restrict__ Cout) {
    __shared__ float As[8][128];   // transposed: As[k][m]
    __shared__ float Bs[8][128];   // Bs[k][n]

    const float* A    = (MODE == 0) ? A_ext  : g_z;
    const float* Bm   = (MODE == 0) ? g_w    : B_ext;
    const float* bias = (MODE == 0) ? g_bias : bias_ext;

    const int tid  = threadIdx.x;
    const int m0   = blockIdx.y * 128;
    const int n0   = blockIdx.x * 128;
    const int trow = tid >> 4;          // 0..15
    const int tcol = tid & 15;          // 0..15
    const int arow = tid >> 1;          // 0..127
    const int acol = (tid & 1) << 2;    // 0 or 4
    const int brow = tid >> 5;          // 0..7
    const int bcol = (tid & 31) << 2;   // 0..124

    const float* Ap = A  + (size_t)(m0 + arow)*DMODEL + acol;
    const float* Bp = Bm + (size_t)brow*NN + n0 + bcol;

    float4 a_n = *(const float4*)Ap;
    float4 b_n = *(const float4*)Bp;
    float acc[8][8] = {};

    for (int kt = 0; kt < DMODEL/8; ++kt) {
        As[acol+0][arow] = a_n.x;
        As[acol+1][arow] = a_n.y;
        As[acol+2][arow] = a_n.z;
        As[acol+3][arow] = a_n.w;
        *(float4*)&Bs[brow][bcol] = b_n;
        __syncthreads();
        if (kt < DMODEL/8 - 1) {
            a_n = *(const float4*)(Ap + (size_t)(kt+1)*8);
            b_n = *(const float4*)(Bp + (size_t)(kt+1)*8*NN);
        }
        #pragma unroll
        for (int kk = 0; kk < 8; ++kk) {
            float a[8], b[8];
            *(float4*)&a[0] = *(const float4*)&As[kk][trow*8];
            *(float4*)&a[4] = *(const float4*)&As[kk][trow*8 + 4];
            *(float4*)&b[0] = *(const float4*)&Bs[kk][tcol*8];
            *(float4*)&b[4] = *(const float4*)&Bs[kk][tcol*8 + 4];
            #pragma unroll
            for (int i = 0; i < 8; ++i)
                #pragma unroll
                for (int j = 0; j < 8; ++j)
                    acc[i][j] = fmaf(a[i], b[j], acc[i][j]);
        }
        __syncthreads();
    }

    float bv8[8];
    #pragma unroll
    for (int j = 0; j < 8; ++j) bv8[j] = bias[n0 + tcol*8 + j];

    if (MODE == 0) {
        // scatter into g_qkv [proj][b][h][s][e]; 8-col group never crosses a
        // 64-col head boundary (tcol*8 is 8-aligned, 64 % 8 == 0).
        const int colbase = n0 + tcol*8;
        const int proj = colbase >> 10;
        const int rem  = colbase & 1023;
        const int h = rem >> 6, e0 = rem & 63;
        #pragma unroll
        for (int i = 0; i < 8; ++i) {
            int row = m0 + trow*8 + i;
            int b = row >> 11, s = row & 2047;
            float* dst = g_qkv + (size_t)proj*PSZ
                       + (((size_t)(b*NH + h))*SEQ + s)*DHEAD + e0;
            float4 o0 = make_float4(acc[i][0]+bv8[0], acc[i][1]+bv8[1],
                                    acc[i][2]+bv8[2], acc[i][3]+bv8[3]);
            float4 o1 = make_float4(acc[i][4]+bv8[4], acc[i][5]+bv8[5],
                                    acc[i][6]+bv8[6], acc[i][7]+bv8[7]);
            *(float4*)dst       = o0;
            *(float4*)(dst + 4) = o1;
        }
    } else {
        #pragma unroll
        for (int i = 0; i < 8; ++i) {
            int row = m0 + trow*8 + i;
            float* dst = Cout + (size_t)row*NN + n0 + tcol*8;
            float4 o0 = make_float4(acc[i][0]+bv8[0], acc[i][1]+bv8[1],
                                    acc[i][2]+bv8[2], acc[i][3]+bv8[3]);
            float4 o1 = make_float4(acc[i][4]+bv8[4], acc[i][5]+bv8[5],
                                    acc[i][6]+bv8[6], acc[i][7]+bv8[7]);
            *(float4*)dst       = o0;
            *(float4*)(dst + 4) = o1;
        }
    }
}

// ---------------------------------------------------------------------------
// Flash attention: one block = 64 query rows of one (b,h); loops over 32 kv
// tiles of 64. 256 threads as 16x16, 4x4 microtiles. Online softmax.
// Dynamic smem: qT/kT/vs/ps each [64][68] floats = 69632 B.
// ---------------------------------------------------------------------------
__global__ __launch_bounds__(256)
void attn_kernel() {
    extern __shared__ float sm[];
    float* qT = sm;                 // [e][r]   64x68
    float* kT = sm + 64*68;         // [e][c]
    float* vs = sm + 2*64*68;       // [c][e]
    float* ps = sm + 3*64*68;       // [r][c]

    const int tid = threadIdx.x;
    const int tx  = tid & 15;
    const int ty  = tid >> 4;
    const int bh  = blockIdx.y;            // b*NH + h
    const int s0  = blockIdx.x * 64;

    // load + transpose + pre-scale q by 1/sqrt(DH)=0.125
    const float* qg = g_qkv + ((size_t)bh*SEQ + s0)*DHEAD;
    for (int t = tid; t < 64*16; t += 256) {
        int r = t >> 4, ec = (t & 15) << 2;
        float4 v = *(const float4*)(qg + (size_t)r*64 + ec);
        qT[(ec+0)*68 + r] = v.x * 0.125f;
        qT[(ec+1)*68 + r] = v.y * 0.125f;
        qT[(ec+2)*68 + r] = v.z * 0.125f;
        qT[(ec+3)*68 + r] = v.w * 0.125f;
    }

    float zacc[4][4] = {};
    float mrow[4] = {-1e30f, -1e30f, -1e30f, -1e30f};
    float lrow[4] = {};

    for (int kt = 0; kt < SEQ/64; ++kt) {
        const float* kg = g_qkv + (size_t)PSZ   + ((size_t)bh*SEQ + kt*64)*DHEAD;
        const float* vg = g_qkv + (size_t)2*PSZ + ((size_t)bh*SEQ + kt*64)*DHEAD;

        __syncthreads();   // previous GEMM2 done reading vs/ps; GEMM1 done with kT
        for (int t = tid; t < 64*16; t += 256) {
            int r = t >> 4, ec = (t & 15) << 2;
            float4 v = *(const float4*)(kg + (size_t)r*64 + ec);
            kT[(ec+0)*68 + r] = v.x;
            kT[(ec+1)*68 + r] = v.y;
            kT[(ec+2)*68 + r] = v.z;
            kT[(ec+3)*68 + r] = v.w;
            float4 w = *(const float4*)(vg + (size_t)r*64 + ec);
            *(float4*)&vs[r*68 + ec] = w;
        }
        __syncthreads();

        // GEMM1: S = (q/8) k^T   (64x64)
        float sacc[4][4] = {};
        #pragma unroll 4
        for (int j = 0; j < 64; ++j) {
            float4 qa = *(const float4*)&qT[j*68 + ty*4];
            float4 kb = *(const float4*)&kT[j*68 + tx*4];
            float qa_[4] = {qa.x, qa.y, qa.z, qa.w};
            float kb_[4] = {kb.x, kb.y, kb.z, kb.w};
            #pragma unroll
            for (int i = 0; i < 4; ++i)
                #pragma unroll
                for (int k = 0; k < 4; ++k)
                    sacc[i][k] = fmaf(qa_[i], kb_[k], sacc[i][k]);
        }

        // online softmax over the 64-key tile (row groups share lanes 16-wide)
        #pragma unroll
        for (int i = 0; i < 4; ++i) {
            float rm = fmaxf(fmaxf(sacc[i][0], sacc[i][1]),
                             fmaxf(sacc[i][2], sacc[i][3]));
            rm = fmaxf(rm, __shfl_xor_sync(0xffffffffu, rm, 1));
            rm = fmaxf(rm, __shfl_xor_sync(0xffffffffu, rm, 2));
            rm = fmaxf(rm, __shfl_xor_sync(0xffffffffu, rm, 4));
            rm = fmaxf(rm, __shfl_xor_sync(0xffffffffu, rm, 8));
            float mnew  = fmaxf(mrow[i], rm);
            float alpha = __expf(mrow[i] - mnew);
            mrow[i] = mnew;
            float psum = 0.f;
            #pragma unroll
            for (int k = 0; k < 4; ++k) {
                float p = __expf(sacc[i][k] - mnew);
                sacc[i][k] = p;
                psum += p;
            }
            psum += __shfl_xor_sync(0xffffffffu, psum, 1);
            psum += __shfl_xor_sync(0xffffffffu, psum, 2);
            psum += __shfl_xor_sync(0xffffffffu, psum, 4);
            psum += __shfl_xor_sync(0xffffffffu, psum, 8);
            lrow[i] = lrow[i]*alpha + psum;
            #pragma unroll
            for (int k = 0; k < 4; ++k) zacc[i][k] *= alpha;
            *(float4*)&ps[(ty*4 + i)*68 + tx*4] =
                make_float4(sacc[i][0], sacc[i][1], sacc[i][2], sacc[i][3]);
        }
        __syncthreads();

        // GEMM2: Z += P V  (64x64)
        #pragma unroll 4
        for (int j = 0; j < 64; ++j) {
            float4 vb = *(const float4*)&vs[j*68 + tx*4];
            float vb_[4] = {vb.x, vb.y, vb.z, vb.w};
            #pragma unroll
            for (int i = 0; i < 4; ++i) {
                float a = ps[(ty*4 + i)*68 + j];
                #pragma unroll
                for (int k = 0; k < 4; ++k)
                    zacc[i][k] = fmaf(a, vb_[k], zacc[i][k]);
            }
        }
    }

    // normalize + write to g_z [b][s][h*64+e]
    const int b = bh >> 4, h = bh & 15;
    #pragma unroll
    for (int i = 0; i < 4; ++i) {
        float inv = 1.0f / lrow[i];
        float4 o = make_float4(zacc[i][0]*inv, zacc[i][1]*inv,
                               zacc[i][2]*inv, zacc[i][3]*inv);
        *(float4*)&g_z[((size_t)b*SEQ + s0 + ty*4 + i)*DMODEL + h*64 + tx*4] = o;
    }
}

// ---------------------------------------------------------------------------
extern "C" void kernel_launch(void* const* d_in, const int* in_sizes, int n_in,
                              void* d_out, int out_size) {
    const float* x  = (const float*)d_in[0];
    const float* Wq = (const float*)d_in[1];
    const float* bq = (const float*)d_in[2];
    const float* Wk = (const float*)d_in[3];
    const float* bk = (const float*)d_in[4];
    const float* Wv = (const float*)d_in[5];
    const float* bv = (const float*)d_in[6];
    const float* Wo = (const float*)d_in[7];
    const float* bo = (const float*)d_in[8];
    float* out = (float*)d_out;

    const int ATTN_SMEM = 4*64*68*4;  // 69632 B
    cudaFuncSetAttribute(attn_kernel,
                         cudaFuncAttributeMaxDynamicSharedMemorySize, ATTN_SMEM);

    // 1) repack qkv weights/biases
    repack_w_kernel<<<(3*DMODEL*DMODEL + 255)/256, 256>>>(Wq, Wk, Wv, bq, bk, bv);

    // 2) fused QKV projection: [8192,1024] x [1024,3072] -> g_qkv
    sgemm_kernel<3*DMODEL, 0><<<dim3(24, 64), 256>>>(x, nullptr, nullptr, nullptr);

    // 3) flash attention per (b,h) -> g_z
    attn_kernel<<<dim3(SEQ/64, BATCH*NH), 256, ATTN_SMEM>>>();

    // 4) output projection: g_z x Wo + bo -> out
    sgemm_kernel<DMODEL, 1><<<dim3(8, 64), 256>>>(nullptr, Wo, bo, out);
}

// round 3
// speedup vs baseline: 1.3541x; 1.3541x over previous
#include <cuda_runtime.h>
#include <cuda_bf16.h>
#include <cstdint>
#include <math.h>

#define BATCH 4
#define SEQ 2048
#define DMODEL 1024
#define NH 16
#define DHEAD 64
#define MTOT (BATCH*SEQ)                 /* 8192 rows */
#define PSZ (BATCH*NH*SEQ*DHEAD)         /* 8,388,608 */

// ---------------- device scratch (no cudaMalloc allowed) ----------------
__device__ __align__(128) float          g_qkv[3*PSZ];               // fp32 q,k,v [proj][b][h][s][e]
__device__ __align__(128) __nv_bfloat16  g_x_hi[MTOT*DMODEL];
__device__ __align__(128) __nv_bfloat16  g_x_lo[MTOT*DMODEL];
__device__ __align__(128) __nv_bfloat16  g_z_hi[MTOT*DMODEL];
__device__ __align__(128) __nv_bfloat16  g_z_lo[MTOT*DMODEL];
__device__ __align__(128) __nv_bfloat16  g_wqkv_hi[3*DMODEL*DMODEL]; // [n=(proj,h,e)][k]
__device__ __align__(128) __nv_bfloat16  g_wqkv_lo[3*DMODEL*DMODEL];
__device__ __align__(128) __nv_bfloat16  g_wo_hi[DMODEL*DMODEL];     // [n][k] = Wo^T
__device__ __align__(128) __nv_bfloat16  g_wo_lo[DMODEL*DMODEL];
__device__ __align__(128) float          g_bqkv[3*DMODEL];

// ---------------- helpers ----------------
__device__ __forceinline__ uint32_t smem_u32(const void* p) {
    uint32_t a;
    asm("{ .reg .u64 t; cvta.to.shared.u64 t, %1; cvt.u32.u64 %0, t; }"
        : "=r"(a) : "l"(p));
    return a;
}
__device__ __forceinline__ void split_bf(float x, __nv_bfloat16& hi, __nv_bfloat16& lo) {
    hi = __float2bfloat16(x);
    lo = __float2bfloat16(x - __bfloat162float(hi));
}
__device__ __forceinline__ uint32_t pack_bf(__nv_bfloat16 a, __nv_bfloat16 b) {
    __nv_bfloat162 t(a, b);
    return *reinterpret_cast<uint32_t*>(&t);
}
__device__ __forceinline__ void cpasync16(uint32_t saddr, const void* g) {
    asm volatile("cp.async.cg.shared.global [%0], [%1], 16;"
                 :: "r"(saddr), "l"(g) : "memory");
}
__device__ __forceinline__ void ldsm4(uint32_t& r0, uint32_t& r1,
                                      uint32_t& r2, uint32_t& r3, uint32_t addr) {
    asm volatile("ldmatrix.sync.aligned.m8n8.x4.shared.b16 {%0,%1,%2,%3}, [%4];"
                 : "=r"(r0), "=r"(r1), "=r"(r2), "=r"(r3) : "r"(addr));
}
__device__ __forceinline__ void mma16816(float* d, const uint32_t* a, const uint32_t* b) {
    asm volatile("mma.sync.aligned.m16n8k16.row.col.f32.bf16.bf16.f32 "
                 "{%0,%1,%2,%3},{%4,%5,%6,%7},{%8,%9},{%0,%1,%2,%3};"
                 : "+f"(d[0]), "+f"(d[1]), "+f"(d[2]), "+f"(d[3])
                 : "r"(a[0]), "r"(a[1]), "r"(a[2]), "r"(a[3]),
                   "r"(b[0]), "r"(b[1]));
}
// swizzled byte offset inside a [128 rows x 64B] bf16 tile
__device__ __forceinline__ uint32_t swz_off(int r, int u) {
    return (uint32_t)(r * 64 + ((u ^ ((r >> 1) & 3)) << 4));
}

// ---------------------------------------------------------------------------
// Preprocess: x fp32 -> bf16 hi/lo
// ---------------------------------------------------------------------------
__global__ void convert_x_kernel(const float* __restrict__ x) {
    size_t i = ((size_t)blockIdx.x * 256 + threadIdx.x) * 4;
    float4 v = *(const float4*)(x + i);
    __nv_bfloat16 h0,h1,h2,h3,l0,l1,l2,l3;
    split_bf(v.x, h0, l0); split_bf(v.y, h1, l1);
    split_bf(v.z, h2, l2); split_bf(v.w, h3, l3);
    *(uint2*)&g_x_hi[i] = make_uint2(pack_bf(h0,h1), pack_bf(h2,h3));
    *(uint2*)&g_x_lo[i] = make_uint2(pack_bf(l0,l1), pack_bf(l2,l3));
}

// ---------------------------------------------------------------------------
// Repack QKV weights [H,D,DH] -> transposed bf16 hi/lo [n=(proj,h,e)][k]
// ---------------------------------------------------------------------------
__global__ void repack_wqkv_kernel(const float* __restrict__ Wq,
                                   const float* __restrict__ Wk,
                                   const float* __restrict__ Wv) {
    __shared__ float t[64][65];
    const int tid = threadIdx.x;
    const int k0 = blockIdx.x * 64;
    const int cy = blockIdx.y;            // 0..47
    const int proj = cy >> 4, h = cy & 15;
    const float* W = (proj == 0) ? Wq : (proj == 1 ? Wk : Wv);
    const float* base = W + (size_t)h * DMODEL * DHEAD;   // [1024][64]
    #pragma unroll
    for (int it = 0; it < 4; ++it) {
        int idx = it*256 + tid;
        int r = idx >> 4;
        int c4 = (idx & 15) << 2;
        float4 v = *(const float4*)(base + (size_t)(k0 + r)*DHEAD + c4);
        t[r][c4+0] = v.x; t[r][c4+1] = v.y; t[r][c4+2] = v.z; t[r][c4+3] = v.w;
    }
    __syncthreads();
    const int n0 = proj*1024 + h*64;
    #pragma unroll
    for (int it = 0; it < 4; ++it) {
        int idx = it*256 + tid;
        int e = idx >> 4;
        int kk = (idx & 15) << 2;
        __nv_bfloat16 hh[4], ll[4];
        #pragma unroll
        for (int j = 0; j < 4; ++j) split_bf(t[kk+j][e], hh[j], ll[j]);
        size_t off = (size_t)(n0 + e)*DMODEL + k0 + kk;
        *(uint2*)&g_wqkv_hi[off] = make_uint2(pack_bf(hh[0],hh[1]), pack_bf(hh[2],hh[3]));
        *(uint2*)&g_wqkv_lo[off] = make_uint2(pack_bf(ll[0],ll[1]), pack_bf(ll[2],ll[3]));
    }
}

// Wo [D,D] -> transposed bf16 hi/lo [n][k]
__global__ void repack_wo_kernel(const float* __restrict__ Wo) {
    __shared__ float t[64][65];
    const int tid = threadIdx.x;
    const int k0 = blockIdx.x * 64;
    const int n0 = blockIdx.y * 64;
    #pragma unroll
    for (int it = 0; it < 4; ++it) {
        int idx = it*256 + tid;
        int r = idx >> 4;
        int c4 = (idx & 15) << 2;
        float4 v = *(const float4*)(Wo + (size_t)(k0 + r)*DMODEL + n0 + c4);
        t[r][c4+0] = v.x; t[r][c4+1] = v.y; t[r][c4+2] = v.z; t[r][c4+3] = v.w;
    }
    __syncthreads();
    #pragma unroll
    for (int it = 0; it < 4; ++it) {
        int idx = it*256 + tid;
        int e = idx >> 4;
        int kk = (idx & 15) << 2;
        __nv_bfloat16 hh[4], ll[4];
        #pragma unroll
        for (int j = 0; j < 4; ++j) split_bf(t[kk+j][e], hh[j], ll[j]);
        size_t off = (size_t)(n0 + e)*DMODEL + k0 + kk;
        *(uint2*)&g_wo_hi[off] = make_uint2(pack_bf(hh[0],hh[1]), pack_bf(hh[2],hh[3]));
        *(uint2*)&g_wo_lo[off] = make_uint2(pack_bf(ll[0],ll[1]), pack_bf(ll[2],ll[3]));
    }
}

__global__ void bias_kernel(const float* __restrict__ bq,
                            const float* __restrict__ bk,
                            const float* __restrict__ bv) {
    int i = blockIdx.x * 256 + threadIdx.x;
    if (i < 3*DMODEL) {
        int proj = i >> 10, r = i & 1023;
        g_bqkv[i] = (proj == 0 ? bq : (proj == 1 ? bk : bv))[r];
    }
}

// ---------------------------------------------------------------------------
// mma.sync bf16x3 GEMM: C[8192, NTOT] = A * B^T (+bias)
// CTA 128x128, 8 warps (2m x 4n), warp tile 64x32, K-chunk 32, cp.async 2-stage.
// SMEM per stage 32KB: Ah | Al | Bh | Bl, each 128x32 bf16 (8KB), swizzled.
// MODE 0: A=g_x hi/lo, B=g_wqkv hi/lo, bias=g_bqkv, scatter to g_qkv.
// MODE 1: A=g_z hi/lo, B=g_wo hi/lo, bias=bo, write Cout.
// ---------------------------------------------------------------------------
#define GEMM_SMEM (2*32768)

template<int MODE>
__global__ __launch_bounds__(256)
void mma_gemm_kernel(const float* __restrict__ bias_ext, float* __restrict__ Cout) {
    extern __shared__ char smem[];
    const uint32_t sbase = smem_u32(smem);
    const int tid  = threadIdx.x;
    const int lane = tid & 31;
    const int wid  = tid >> 5;
    const int wm   = wid & 1;          // 0..1
    const int wn   = wid >> 1;         // 0..3
    const int m0 = blockIdx.y * 128;
    const int n0 = blockIdx.x * 128;

    const __nv_bfloat16* Ah = (MODE == 0) ? g_x_hi : g_z_hi;
    const __nv_bfloat16* Al = (MODE == 0) ? g_x_lo : g_z_lo;
    const __nv_bfloat16* Bh = (MODE == 0) ? g_wqkv_hi : g_wo_hi;
    const __nv_bfloat16* Bl = (MODE == 0) ? g_wqkv_lo : g_wo_lo;

    // per-thread cp.async descriptors: 8 x 16B per stage
    const __nv_bfloat16* gsrc[8];
    uint32_t soff[8];
    #pragma unroll
    for (int c = 0; c < 8; ++c) {
        int linear = c*256 + tid;          // 0..2047
        int tile = linear >> 9;            // 0:Ah 1:Al 2:Bh 3:Bl
        int idx  = linear & 511;
        int r = idx >> 2, u = idx & 3;
        const __nv_bfloat16* bp = (tile == 0) ? Ah : (tile == 1) ? Al
                                 : (tile == 2) ? Bh : Bl;
        int rowbase = (tile < 2) ? m0 : n0;
        gsrc[c] = bp + (size_t)(rowbase + r)*DMODEL + u*8;
        soff[c] = (uint32_t)tile*8192u + swz_off(r, u);
    }

    // ldmatrix lane geometry
    const int a_r  = lane & 15;
    const int lu   = lane >> 4;                          // k-half select
    const int b_r  = (lane & 7) + ((lane >> 3) & 1) * 8; // n row within 16

    float acc[4][4][4] = {};

    // prologue: stage 0
    #pragma unroll
    for (int c = 0; c < 8; ++c) cpasync16(sbase + soff[c], gsrc[c]);
    asm volatile("cp.async.commit_group;" ::: "memory");

    #pragma unroll 1
    for (int kt = 0; kt < DMODEL/32; ++kt) {
        if (kt + 1 < DMODEL/32) {
            uint32_t st = sbase + ((kt + 1) & 1) * 32768u;
            #pragma unroll
            for (int c = 0; c < 8; ++c)
                cpasync16(st + soff[c], gsrc[c] + (kt + 1)*32);
            asm volatile("cp.async.commit_group;" ::: "memory");
            asm volatile("cp.async.wait_group 1;" ::: "memory");
        } else {
            asm volatile("cp.async.wait_group 0;" ::: "memory");
        }
        __syncthreads();

        const uint32_t st = sbase + (kt & 1) * 32768u;
        #pragma unroll
        for (int ks = 0; ks < 2; ++ks) {
            const int u = ks*2 + lu;
            uint32_t ah[4][4], al[4][4];
            #pragma unroll
            for (int mi = 0; mi < 4; ++mi) {
                int r = wm*64 + mi*16 + a_r;
                uint32_t so = swz_off(r, u);
                ldsm4(ah[mi][0], ah[mi][1], ah[mi][2], ah[mi][3], st + so);
                ldsm4(al[mi][0], al[mi][1], al[mi][2], al[mi][3], st + 8192u + so);
            }
            uint32_t bh[4][2], bl[4][2];
            #pragma unroll
            for (int g = 0; g < 2; ++g) {
                int r = wn*32 + g*16 + b_r;
                uint32_t so = swz_off(r, u);
                uint32_t t0, t1, t2, t3;
                ldsm4(t0, t1, t2, t3, st + 16384u + so);
                bh[g*2][0] = t0; bh[g*2][1] = t2;
                bh[g*2+1][0] = t1; bh[g*2+1][1] = t3;
                ldsm4(t0, t1, t2, t3, st + 24576u + so);
                bl[g*2][0] = t0; bl[g*2][1] = t2;
                bl[g*2+1][0] = t1; bl[g*2+1][1] = t3;
            }
            #pragma unroll
            for (int mi = 0; mi < 4; ++mi)
                #pragma unroll
                for (int nb = 0; nb < 4; ++nb) {
                    mma16816(acc[mi][nb], ah[mi], bh[nb]);
                    mma16816(acc[mi][nb], ah[mi], bl[nb]);
                    mma16816(acc[mi][nb], al[mi], bh[nb]);
                }
        }
        __syncthreads();
    }

    // epilogue
    const float* bias = (MODE == 0) ? g_bqkv : bias_ext;
    #pragma unroll
    for (int nb = 0; nb < 4; ++nb) {
        const int ncol = n0 + wn*32 + nb*8 + (lane & 3)*2;
        const float b0 = bias[ncol], b1 = bias[ncol + 1];
        #pragma unroll
        for (int mi = 0; mi < 4; ++mi) {
            const int m = m0 + wm*64 + mi*16 + (lane >> 2);
            if (MODE == 0) {
                const int proj = ncol >> 10, h = (ncol >> 6) & 15, e0 = ncol & 63;
                const int b = m >> 11;
                float* base = g_qkv + (size_t)proj*PSZ
                            + (((size_t)(b*NH + h))*SEQ)*DHEAD + e0;
                float2 o0 = make_float2(acc[mi][nb][0] + b0, acc[mi][nb][1] + b1);
                float2 o1 = make_float2(acc[mi][nb][2] + b0, acc[mi][nb][3] + b1);
                *(float2*)(base + (size_t)(m & 2047)*DHEAD)       = o0;
                *(float2*)(base + (size_t)((m + 8) & 2047)*DHEAD) = o1;
            } else {
                float2 o0 = make_float2(acc[mi][nb][0] + b0, acc[mi][nb][1] + b1);
                float2 o1 = make_float2(acc[mi][nb][2] + b0, acc[mi][nb][3] + b1);
                *(float2*)(Cout + (size_t)m*DMODEL + ncol)       = o0;
                *(float2*)(Cout + (size_t)(m + 8)*DMODEL + ncol) = o1;
            }
        }
    }
}

// ---------------------------------------------------------------------------
// Flash attention (fp32 SIMT); epilogue writes bf16 hi/lo z.
// ---------------------------------------------------------------------------
__global__ __launch_bounds__(256)
void attn_kernel() {
    extern __shared__ float sm[];
    float* qT = sm;                 // [e][r]   64x68
    float* kT = sm + 64*68;         // [e][c]
    float* vs = sm + 2*64*68;       // [c][e]
    float* ps = sm + 3*64*68;       // [r][c]

    const int tid = threadIdx.x;
    const int tx  = tid & 15;
    const int ty  = tid >> 4;
    const int bh  = blockIdx.y;
    const int s0  = blockIdx.x * 64;

    const float* qg = g_qkv + ((size_t)bh*SEQ + s0)*DHEAD;
    for (int t = tid; t < 64*16; t += 256) {
        int r = t >> 4, ec = (t & 15) << 2;
        float4 v = *(const float4*)(qg + (size_t)r*64 + ec);
        qT[(ec+0)*68 + r] = v.x * 0.125f;
        qT[(ec+1)*68 + r] = v.y * 0.125f;
        qT[(ec+2)*68 + r] = v.z * 0.125f;
        qT[(ec+3)*68 + r] = v.w * 0.125f;
    }

    float zacc[4][4] = {};
    float mrow[4] = {-1e30f, -1e30f, -1e30f, -1e30f};
    float lrow[4] = {};

    for (int kt = 0; kt < SEQ/64; ++kt) {
        const float* kg = g_qkv + (size_t)PSZ   + ((size_t)bh*SEQ + kt*64)*DHEAD;
        const float* vg = g_qkv + (size_t)2*PSZ + ((size_t)bh*SEQ + kt*64)*DHEAD;

        __syncthreads();
        for (int t = tid; t < 64*16; t += 256) {
            int r = t >> 4, ec = (t & 15) << 2;
            float4 v = *(const float4*)(kg + (size_t)r*64 + ec);
            kT[(ec+0)*68 + r] = v.x;
            kT[(ec+1)*68 + r] = v.y;
            kT[(ec+2)*68 + r] = v.z;
            kT[(ec+3)*68 + r] = v.w;
            float4 w = *(const float4*)(vg + (size_t)r*64 + ec);
            *(float4*)&vs[r*68 + ec] = w;
        }
        __syncthreads();

        float sacc[4][4] = {};
        #pragma unroll 4
        for (int j = 0; j < 64; ++j) {
            float4 qa = *(const float4*)&qT[j*68 + ty*4];
            float4 kb = *(const float4*)&kT[j*68 + tx*4];
            float qa_[4] = {qa.x, qa.y, qa.z, qa.w};
            float kb_[4] = {kb.x, kb.y, kb.z, kb.w};
            #pragma unroll
            for (int i = 0; i < 4; ++i)
                #pragma unroll
                for (int k = 0; k < 4; ++k)
                    sacc[i][k] = fmaf(qa_[i], kb_[k], sacc[i][k]);
        }

        #pragma unroll
        for (int i = 0; i < 4; ++i) {
            float rm = fmaxf(fmaxf(sacc[i][0], sacc[i][1]),
                             fmaxf(sacc[i][2], sacc[i][3]));
            rm = fmaxf(rm, __shfl_xor_sync(0xffffffffu, rm, 1));
            rm = fmaxf(rm, __shfl_xor_sync(0xffffffffu, rm, 2));
            rm = fmaxf(rm, __shfl_xor_sync(0xffffffffu, rm, 4));
            rm = fmaxf(rm, __shfl_xor_sync(0xffffffffu, rm, 8));
            float mnew  = fmaxf(mrow[i], rm);
            float alpha = __expf(mrow[i] - mnew);
            mrow[i] = mnew;
            float psum = 0.f;
            #pragma unroll
            for (int k = 0; k < 4; ++k) {
                float p = __expf(sacc[i][k] - mnew);
                sacc[i][k] = p;
                psum += p;
            }
            psum += __shfl_xor_sync(0xffffffffu, psum, 1);
            psum += __shfl_xor_sync(0xffffffffu, psum, 2);
            psum += __shfl_xor_sync(0xffffffffu, psum, 4);
            psum += __shfl_xor_sync(0xffffffffu, psum, 8);
            lrow[i] = lrow[i]*alpha + psum;
            #pragma unroll
            for (int k = 0; k < 4; ++k) zacc[i][k] *= alpha;
            *(float4*)&ps[(ty*4 + i)*68 + tx*4] =
                make_float4(sacc[i][0], sacc[i][1], sacc[i][2], sacc[i][3]);
        }
        __syncthreads();

        #pragma unroll 4
        for (int j = 0; j < 64; ++j) {
            float4 vb = *(const float4*)&vs[j*68 + tx*4];
            float vb_[4] = {vb.x, vb.y, vb.z, vb.w};
            #pragma unroll
            for (int i = 0; i < 4; ++i) {
                float a = ps[(ty*4 + i)*68 + j];
                #pragma unroll
                for (int k = 0; k < 4; ++k)
                    zacc[i][k] = fmaf(a, vb_[k], zacc[i][k]);
            }
        }
    }

    const int b = bh >> 4, h = bh & 15;
    #pragma unroll
    for (int i = 0; i < 4; ++i) {
        float inv = 1.0f / lrow[i];
        float v0 = zacc[i][0]*inv, v1 = zacc[i][1]*inv;
        float v2 = zacc[i][2]*inv, v3 = zacc[i][3]*inv;
        __nv_bfloat16 h0,h1,h2,h3,l0,l1,l2,l3;
        split_bf(v0, h0, l0); split_bf(v1, h1, l1);
        split_bf(v2, h2, l2); split_bf(v3, h3, l3);
        size_t base = ((size_t)b*SEQ + s0 + ty*4 + i)*DMODEL + h*64 + tx*4;
        *(uint2*)&g_z_hi[base] = make_uint2(pack_bf(h0,h1), pack_bf(h2,h3));
        *(uint2*)&g_z_lo[base] = make_uint2(pack_bf(l0,l1), pack_bf(l2,l3));
    }
}

// ---------------------------------------------------------------------------
extern "C" void kernel_launch(void* const* d_in, const int* in_sizes, int n_in,
                              void* d_out, int out_size) {
    const float* x  = (const float*)d_in[0];
    const float* Wq = (const float*)d_in[1];
    const float* bq = (const float*)d_in[2];
    const float* Wk = (const float*)d_in[3];
    const float* bk = (const float*)d_in[4];
    const float* Wv = (const float*)d_in[5];
    const float* bv = (const float*)d_in[6];
    const float* Wo = (const float*)d_in[7];
    const float* bo = (const float*)d_in[8];
    float* out = (float*)d_out;

    const int ATTN_SMEM = 4*64*68*4;  // 69632 B
    cudaFuncSetAttribute(attn_kernel,
                         cudaFuncAttributeMaxDynamicSharedMemorySize, ATTN_SMEM);
    cudaFuncSetAttribute(mma_gemm_kernel<0>,
                         cudaFuncAttributeMaxDynamicSharedMemorySize, GEMM_SMEM);
    cudaFuncSetAttribute(mma_gemm_kernel<1>,
                         cudaFuncAttributeMaxDynamicSharedMemorySize, GEMM_SMEM);

    // preprocessing
    convert_x_kernel<<<(MTOT*DMODEL)/1024, 256>>>(x);
    repack_wqkv_kernel<<<dim3(16, 48), 256>>>(Wq, Wk, Wv);
    repack_wo_kernel<<<dim3(16, 16), 256>>>(Wo);
    bias_kernel<<<12, 256>>>(bq, bk, bv);

    // QKV projection (mma.sync bf16x3): [8192,1024] x [3072,1024]^T -> g_qkv
    mma_gemm_kernel<0><<<dim3(24, 64), 256, GEMM_SMEM>>>(nullptr, nullptr);

    // flash attention per (b,h) -> g_z (bf16 hi/lo)
    attn_kernel<<<dim3(SEQ/64, BATCH*NH), 256, ATTN_SMEM>>>();

    // output projection (mma.sync bf16x3) -> out
    mma_gemm_kernel<1><<<dim3(8, 64), 256, GEMM_SMEM>>>(bo, out);
}

// round 5
// speedup vs baseline: 2.7803x; 2.0532x over previous
#include <cuda_runtime.h>
#include <cuda_bf16.h>
#include <cstdint>
#include <math.h>

#define BATCH 4
#define SEQ 2048
#define DMODEL 1024
#define NH 16
#define DHEAD 64
#define MTOT (BATCH*SEQ)                 /* 8192 rows */
#define PSZ (BATCH*NH*SEQ*DHEAD)         /* 8,388,608 */
#define BQ 128
#define BK 64

// ---------------- device scratch ----------------
__device__ __align__(128) __nv_bfloat16  g_qkv_hi[3*PSZ];            // [proj][bh][s][e], q pre-scaled by 1/8
__device__ __align__(128) __nv_bfloat16  g_qkv_lo[3*PSZ];
__device__ __align__(128) __nv_bfloat16  g_x_hi[MTOT*DMODEL];
__device__ __align__(128) __nv_bfloat16  g_x_lo[MTOT*DMODEL];
__device__ __align__(128) __nv_bfloat16  g_z_hi[MTOT*DMODEL];
__device__ __align__(128) __nv_bfloat16  g_z_lo[MTOT*DMODEL];
__device__ __align__(128) __nv_bfloat16  g_wqkv_hi[3*DMODEL*DMODEL]; // [n=(proj,h,e)][k]
__device__ __align__(128) __nv_bfloat16  g_wqkv_lo[3*DMODEL*DMODEL];
__device__ __align__(128) __nv_bfloat16  g_wo_hi[DMODEL*DMODEL];     // [n][k] = Wo^T
__device__ __align__(128) __nv_bfloat16  g_wo_lo[DMODEL*DMODEL];
__device__ __align__(128) float          g_bqkv[3*DMODEL];

// ---------------- helpers ----------------
__device__ __forceinline__ uint32_t smem_u32(const void* p) {
    uint32_t a;
    asm("{ .reg .u64 t; cvta.to.shared.u64 t, %1; cvt.u32.u64 %0, t; }"
        : "=r"(a) : "l"(p));
    return a;
}
__device__ __forceinline__ void split_bf(float x, __nv_bfloat16& hi, __nv_bfloat16& lo) {
    hi = __float2bfloat16(x);
    lo = __float2bfloat16(x - __bfloat162float(hi));
}
__device__ __forceinline__ uint32_t pack_bf(__nv_bfloat16 a, __nv_bfloat16 b) {
    __nv_bfloat162 t(a, b);
    return *reinterpret_cast<uint32_t*>(&t);
}
__device__ __forceinline__ void cpasync16(uint32_t saddr, const void* g) {
    asm volatile("cp.async.cg.shared.global [%0], [%1], 16;"
                 :: "r"(saddr), "l"(g) : "memory");
}
__device__ __forceinline__ void ldsm4(uint32_t& r0, uint32_t& r1,
                                      uint32_t& r2, uint32_t& r3, uint32_t addr) {
    asm volatile("ldmatrix.sync.aligned.m8n8.x4.shared.b16 {%0,%1,%2,%3}, [%4];"
                 : "=r"(r0), "=r"(r1), "=r"(r2), "=r"(r3) : "r"(addr));
}
__device__ __forceinline__ void ldsm4t(uint32_t& r0, uint32_t& r1,
                                       uint32_t& r2, uint32_t& r3, uint32_t addr) {
    asm volatile("ldmatrix.sync.aligned.m8n8.x4.trans.shared.b16 {%0,%1,%2,%3}, [%4];"
                 : "=r"(r0), "=r"(r1), "=r"(r2), "=r"(r3) : "r"(addr));
}
__device__ __forceinline__ void mma16816(float* d, const uint32_t* a, const uint32_t* b) {
    asm volatile("mma.sync.aligned.m16n8k16.row.col.f32.bf16.bf16.f32 "
                 "{%0,%1,%2,%3},{%4,%5,%6,%7},{%8,%9},{%0,%1,%2,%3};"
                 : "+f"(d[0]), "+f"(d[1]), "+f"(d[2]), "+f"(d[3])
                 : "r"(a[0]), "r"(a[1]), "r"(a[2]), "r"(a[3]),
                   "r"(b[0]), "r"(b[1]));
}
// swizzle for [rows x 64B] tiles (4 x 16B units)
__device__ __forceinline__ uint32_t swz_off(int r, int u) {
    return (uint32_t)(r * 64 + ((u ^ ((r >> 1) & 3)) << 4));
}
// swizzle for [rows x 128B] tiles (8 x 16B units)
__device__ __forceinline__ uint32_t swz128(int r, int u) {
    return (uint32_t)(r * 128 + ((u ^ (r & 7)) << 4));
}

// ---------------------------------------------------------------------------
// Preprocess kernels
// ---------------------------------------------------------------------------
__global__ void convert_x_kernel(const float* __restrict__ x) {
    size_t i = ((size_t)blockIdx.x * 256 + threadIdx.x) * 4;
    float4 v = *(const float4*)(x + i);
    __nv_bfloat16 h0,h1,h2,h3,l0,l1,l2,l3;
    split_bf(v.x, h0, l0); split_bf(v.y, h1, l1);
    split_bf(v.z, h2, l2); split_bf(v.w, h3, l3);
    *(uint2*)&g_x_hi[i] = make_uint2(pack_bf(h0,h1), pack_bf(h2,h3));
    *(uint2*)&g_x_lo[i] = make_uint2(pack_bf(l0,l1), pack_bf(l2,l3));
}

__global__ void repack_wqkv_kernel(const float* __restrict__ Wq,
                                   const float* __restrict__ Wk,
                                   const float* __restrict__ Wv) {
    __shared__ float t[64][65];
    const int tid = threadIdx.x;
    const int k0 = blockIdx.x * 64;
    const int cy = blockIdx.y;            // 0..47
    const int proj = cy >> 4, h = cy & 15;
    const float* W = (proj == 0) ? Wq : (proj == 1 ? Wk : Wv);
    const float* base = W + (size_t)h * DMODEL * DHEAD;
    #pragma unroll
    for (int it = 0; it < 4; ++it) {
        int idx = it*256 + tid;
        int r = idx >> 4;
        int c4 = (idx & 15) << 2;
        float4 v = *(const float4*)(base + (size_t)(k0 + r)*DHEAD + c4);
        t[r][c4+0] = v.x; t[r][c4+1] = v.y; t[r][c4+2] = v.z; t[r][c4+3] = v.w;
    }
    __syncthreads();
    const int n0 = proj*1024 + h*64;
    #pragma unroll
    for (int it = 0; it < 4; ++it) {
        int idx = it*256 + tid;
        int e = idx >> 4;
        int kk = (idx & 15) << 2;
        __nv_bfloat16 hh[4], ll[4];
        #pragma unroll
        for (int j = 0; j < 4; ++j) split_bf(t[kk+j][e], hh[j], ll[j]);
        size_t off = (size_t)(n0 + e)*DMODEL + k0 + kk;
        *(uint2*)&g_wqkv_hi[off] = make_uint2(pack_bf(hh[0],hh[1]), pack_bf(hh[2],hh[3]));
        *(uint2*)&g_wqkv_lo[off] = make_uint2(pack_bf(ll[0],ll[1]), pack_bf(ll[2],ll[3]));
    }
}

__global__ void repack_wo_kernel(const float* __restrict__ Wo) {
    __shared__ float t[64][65];
    const int tid = threadIdx.x;
    const int k0 = blockIdx.x * 64;
    const int n0 = blockIdx.y * 64;
    #pragma unroll
    for (int it = 0; it < 4; ++it) {
        int idx = it*256 + tid;
        int r = idx >> 4;
        int c4 = (idx & 15) << 2;
        float4 v = *(const float4*)(Wo + (size_t)(k0 + r)*DMODEL + n0 + c4);
        t[r][c4+0] = v.x; t[r][c4+1] = v.y; t[r][c4+2] = v.z; t[r][c4+3] = v.w;
    }
    __syncthreads();
    #pragma unroll
    for (int it = 0; it < 4; ++it) {
        int idx = it*256 + tid;
        int e = idx >> 4;
        int kk = (idx & 15) << 2;
        __nv_bfloat16 hh[4], ll[4];
        #pragma unroll
        for (int j = 0; j < 4; ++j) split_bf(t[kk+j][e], hh[j], ll[j]);
        size_t off = (size_t)(n0 + e)*DMODEL + k0 + kk;
        *(uint2*)&g_wo_hi[off] = make_uint2(pack_bf(hh[0],hh[1]), pack_bf(hh[2],hh[3]));
        *(uint2*)&g_wo_lo[off] = make_uint2(pack_bf(ll[0],ll[1]), pack_bf(ll[2],ll[3]));
    }
}

__global__ void bias_kernel(const float* __restrict__ bq,
                            const float* __restrict__ bk,
                            const float* __restrict__ bv) {
    int i = blockIdx.x * 256 + threadIdx.x;
    if (i < 3*DMODEL) {
        int proj = i >> 10, r = i & 1023;
        g_bqkv[i] = (proj == 0 ? bq : (proj == 1 ? bk : bv))[r];
    }
}

// ---------------------------------------------------------------------------
// mma.sync bf16x3 GEMM: C[8192, NTOT] = A * B^T (+bias)
// MODE 0: A=g_x hi/lo, B=g_wqkv hi/lo, bias=g_bqkv -> g_qkv_hi/lo bf16 (q scaled 1/8)
// MODE 1: A=g_z hi/lo, B=g_wo hi/lo, bias=bo -> Cout fp32
// ---------------------------------------------------------------------------
#define GEMM_SMEM (2*32768)

template<int MODE>
__global__ __launch_bounds__(256)
void mma_gemm_kernel(const float* __restrict__ bias_ext, float* __restrict__ Cout) {
    extern __shared__ char smem[];
    const uint32_t sbase = smem_u32(smem);
    const int tid  = threadIdx.x;
    const int lane = tid & 31;
    const int wid  = tid >> 5;
    const int wm   = wid & 1;
    const int wn   = wid >> 1;
    const int m0 = blockIdx.y * 128;
    const int n0 = blockIdx.x * 128;

    const __nv_bfloat16* Ah = (MODE == 0) ? g_x_hi : g_z_hi;
    const __nv_bfloat16* Al = (MODE == 0) ? g_x_lo : g_z_lo;
    const __nv_bfloat16* Bh = (MODE == 0) ? g_wqkv_hi : g_wo_hi;
    const __nv_bfloat16* Bl = (MODE == 0) ? g_wqkv_lo : g_wo_lo;

    const __nv_bfloat16* gsrc[8];
    uint32_t soff[8];
    #pragma unroll
    for (int c = 0; c < 8; ++c) {
        int linear = c*256 + tid;
        int tile = linear >> 9;            // 0:Ah 1:Al 2:Bh 3:Bl
        int idx  = linear & 511;
        int r = idx >> 2, u = idx & 3;
        const __nv_bfloat16* bp = (tile == 0) ? Ah : (tile == 1) ? Al
                                 : (tile == 2) ? Bh : Bl;
        int rowbase = (tile < 2) ? m0 : n0;
        gsrc[c] = bp + (size_t)(rowbase + r)*DMODEL + u*8;
        soff[c] = (uint32_t)tile*8192u + swz_off(r, u);
    }

    const int a_r  = lane & 15;
    const int lu   = lane >> 4;
    const int b_r  = (lane & 7) + ((lane >> 3) & 1) * 8;

    float acc[4][4][4] = {};

    #pragma unroll
    for (int c = 0; c < 8; ++c) cpasync16(sbase + soff[c], gsrc[c]);
    asm volatile("cp.async.commit_group;" ::: "memory");

    #pragma unroll 1
    for (int kt = 0; kt < DMODEL/32; ++kt) {
        if (kt + 1 < DMODEL/32) {
            uint32_t st = sbase + ((kt + 1) & 1) * 32768u;
            #pragma unroll
            for (int c = 0; c < 8; ++c)
                cpasync16(st + soff[c], gsrc[c] + (kt + 1)*32);
            asm volatile("cp.async.commit_group;" ::: "memory");
            asm volatile("cp.async.wait_group 1;" ::: "memory");
        } else {
            asm volatile("cp.async.wait_group 0;" ::: "memory");
        }
        __syncthreads();

        const uint32_t st = sbase + (kt & 1) * 32768u;
        #pragma unroll
        for (int ks = 0; ks < 2; ++ks) {
            const int u = ks*2 + lu;
            uint32_t ah[4][4], al[4][4];
            #pragma unroll
            for (int mi = 0; mi < 4; ++mi) {
                int r = wm*64 + mi*16 + a_r;
                uint32_t so = swz_off(r, u);
                ldsm4(ah[mi][0], ah[mi][1], ah[mi][2], ah[mi][3], st + so);
                ldsm4(al[mi][0], al[mi][1], al[mi][2], al[mi][3], st + 8192u + so);
            }
            uint32_t bh[4][2], bl[4][2];
            #pragma unroll
            for (int g = 0; g < 2; ++g) {
                int r = wn*32 + g*16 + b_r;
                uint32_t so = swz_off(r, u);
                uint32_t t0, t1, t2, t3;
                ldsm4(t0, t1, t2, t3, st + 16384u + so);
                bh[g*2][0] = t0; bh[g*2][1] = t2;
                bh[g*2+1][0] = t1; bh[g*2+1][1] = t3;
                ldsm4(t0, t1, t2, t3, st + 24576u + so);
                bl[g*2][0] = t0; bl[g*2][1] = t2;
                bl[g*2+1][0] = t1; bl[g*2+1][1] = t3;
            }
            #pragma unroll
            for (int mi = 0; mi < 4; ++mi)
                #pragma unroll
                for (int nb = 0; nb < 4; ++nb) {
                    mma16816(acc[mi][nb], ah[mi], bh[nb]);
                    mma16816(acc[mi][nb], ah[mi], bl[nb]);
                    mma16816(acc[mi][nb], al[mi], bh[nb]);
                }
        }
        __syncthreads();
    }

    // epilogue
    const float* bias = (MODE == 0) ? g_bqkv : bias_ext;
    #pragma unroll
    for (int nb = 0; nb < 4; ++nb) {
        const int ncol = n0 + wn*32 + nb*8 + (lane & 3)*2;
        const float b0 = bias[ncol], b1 = bias[ncol + 1];
        #pragma unroll
        for (int mi = 0; mi < 4; ++mi) {
            const int m = m0 + wm*64 + mi*16 + (lane >> 2);
            float v00 = acc[mi][nb][0] + b0, v01 = acc[mi][nb][1] + b1; // row m
            float v10 = acc[mi][nb][2] + b0, v11 = acc[mi][nb][3] + b1; // row m+8
            if (MODE == 0) {
                const int proj = ncol >> 10, h = (ncol >> 6) & 15, e0 = ncol & 63;
                if (proj == 0) { v00 *= 0.125f; v01 *= 0.125f; v10 *= 0.125f; v11 *= 0.125f; }
                const int b = m >> 11, s = m & 2047;
                size_t base = (size_t)proj*PSZ
                            + (((size_t)(b*NH + h))*SEQ + s)*DHEAD + e0;
                __nv_bfloat16 h0,h1,l0,l1;
                split_bf(v00, h0, l0); split_bf(v01, h1, l1);
                *(uint32_t*)&g_qkv_hi[base] = pack_bf(h0, h1);
                *(uint32_t*)&g_qkv_lo[base] = pack_bf(l0, l1);
                split_bf(v10, h0, l0); split_bf(v11, h1, l1);
                *(uint32_t*)&g_qkv_hi[base + 8*DHEAD] = pack_bf(h0, h1);
                *(uint32_t*)&g_qkv_lo[base + 8*DHEAD] = pack_bf(l0, l1);
            } else {
                *(float2*)(Cout + (size_t)m*DMODEL + ncol)       = make_float2(v00, v01);
                *(float2*)(Cout + (size_t)(m + 8)*DMODEL + ncol) = make_float2(v10, v11);
            }
        }
    }
}

// ---------------------------------------------------------------------------
// Flash attention via mma.sync bf16x3.
// CTA = 128 q rows of one (b,h); 8 warps x 16 rows; KV tiles of 64, 2-stage.
// SMEM map (bytes):
//   [0, 16384)        Qh [128][64] bf16
//   [16384, 32768)    Ql [128][64] bf16
//   [32768 + s*32768) stage s: Kh(8K) | Kl(8K) | Vh(8K) | Vl(8K), each [64][64]
// ---------------------------------------------------------------------------
#define ATTN_SMEM (32768 + 2*32768)

__global__ __launch_bounds__(256)
void attn_mma_kernel() {
    extern __shared__ char smem[];
    const uint32_t sb = smem_u32(smem);
    const int tid  = threadIdx.x;
    const int lane = tid & 31;
    const int w    = tid >> 5;
    const int bh   = blockIdx.y;
    const int s0   = blockIdx.x * BQ;

    const __nv_bfloat16* qh_g = g_qkv_hi + ((size_t)bh*SEQ + s0)*DHEAD;
    const __nv_bfloat16* ql_g = g_qkv_lo + ((size_t)bh*SEQ + s0)*DHEAD;
    const __nv_bfloat16* kh_g = g_qkv_hi + (size_t)PSZ   + (size_t)bh*SEQ*DHEAD;
    const __nv_bfloat16* kl_g = g_qkv_lo + (size_t)PSZ   + (size_t)bh*SEQ*DHEAD;
    const __nv_bfloat16* vh_g = g_qkv_hi + (size_t)2*PSZ + (size_t)bh*SEQ*DHEAD;
    const __nv_bfloat16* vl_g = g_qkv_lo + (size_t)2*PSZ + (size_t)bh*SEQ*DHEAD;

    // Q fill: Qh at 0, Ql at 16384
    #pragma unroll
    for (int c = 0; c < 8; ++c) {
        int linear = c*256 + tid;
        int half = linear >> 10;
        int idx  = linear & 1023;
        int r = idx >> 3, u = idx & 7;
        const __nv_bfloat16* src = (half ? ql_g : qh_g) + (size_t)r*DHEAD + u*8;
        cpasync16(sb + half*16384u + swz128(r, u), src);
    }
    // KV per-thread descriptors
    const __nv_bfloat16* t_src[8];
    uint32_t t_soff[8];
    #pragma unroll
    for (int c = 0; c < 8; ++c) {
        int linear = c*256 + tid;
        int tile = linear >> 9;            // 0:Kh 1:Kl 2:Vh 3:Vl
        int idx  = linear & 511;
        int r = idx >> 3, u = idx & 7;
        const __nv_bfloat16* base = (tile == 0) ? kh_g : (tile == 1) ? kl_g
                                   : (tile == 2) ? vh_g : vl_g;
        t_src[c] = base + (size_t)r*DHEAD + u*8;
        t_soff[c] = (uint32_t)tile*8192u + swz128(r, u);
    }
    // stage 0 fill
    #pragma unroll
    for (int c = 0; c < 8; ++c) cpasync16(sb + 32768u + t_soff[c], t_src[c]);
    asm volatile("cp.async.commit_group;" ::: "memory");
    asm volatile("cp.async.wait_group 0;" ::: "memory");
    __syncthreads();

    const int a_r = lane & 15;
    const int lu  = lane >> 4;
    const int b_r = (lane & 7) + ((lane >> 3) & 1) * 8;

    // Q fragments (held in registers for the whole kernel)
    uint32_t qh[4][4], ql[4][4];
    #pragma unroll
    for (int ks = 0; ks < 4; ++ks) {
        uint32_t so = swz128(w*16 + a_r, ks*2 + lu);
        ldsm4(qh[ks][0], qh[ks][1], qh[ks][2], qh[ks][3], sb + so);
        ldsm4(ql[ks][0], ql[ks][1], ql[ks][2], ql[ks][3], sb + 16384u + so);
    }

    float oacc[8][4] = {};
    float m0 = -1e30f, m1 = -1e30f, l0 = 0.f, l1 = 0.f;

    #pragma unroll 1
    for (int kt = 0; kt < SEQ/BK; ++kt) {
        if (kt + 1 < SEQ/BK) {
            uint32_t st = sb + 32768u + ((kt + 1) & 1) * 32768u;
            #pragma unroll
            for (int c = 0; c < 8; ++c)
                cpasync16(st + t_soff[c], t_src[c] + (size_t)(kt + 1)*BK*DHEAD);
            asm volatile("cp.async.commit_group;" ::: "memory");
            asm volatile("cp.async.wait_group 1;" ::: "memory");
        } else {
            asm volatile("cp.async.wait_group 0;" ::: "memory");
        }
        __syncthreads();
        const uint32_t st = sb + 32768u + (kt & 1) * 32768u;

        // ---- QK: S = (q/8) k^T (bf16x3) ----
        float sacc[8][4] = {};
        #pragma unroll
        for (int ks = 0; ks < 4; ++ks) {
            uint32_t kh2[8][2], kl2[8][2];
            #pragma unroll
            for (int g = 0; g < 4; ++g) {
                uint32_t so = swz128(g*16 + b_r, ks*2 + lu);
                uint32_t t0, t1, t2, t3;
                ldsm4(t0, t1, t2, t3, st + so);
                kh2[g*2][0] = t0; kh2[g*2][1] = t2;
                kh2[g*2+1][0] = t1; kh2[g*2+1][1] = t3;
                ldsm4(t0, t1, t2, t3, st + 8192u + so);
                kl2[g*2][0] = t0; kl2[g*2][1] = t2;
                kl2[g*2+1][0] = t1; kl2[g*2+1][1] = t3;
            }
            #pragma unroll
            for (int nb = 0; nb < 8; ++nb) {
                mma16816(sacc[nb], qh[ks], kh2[nb]);
                mma16816(sacc[nb], qh[ks], kl2[nb]);
                mma16816(sacc[nb], ql[ks], kh2[nb]);
            }
        }

        // ---- online softmax (rows r=lane>>2 and r+8) ----
        float tm0 = -1e30f, tm1 = -1e30f;
        #pragma unroll
        for (int nb = 0; nb < 8; ++nb) {
            tm0 = fmaxf(tm0, fmaxf(sacc[nb][0], sacc[nb][1]));
            tm1 = fmaxf(tm1, fmaxf(sacc[nb][2], sacc[nb][3]));
        }
        tm0 = fmaxf(tm0, __shfl_xor_sync(0xffffffffu, tm0, 1));
        tm0 = fmaxf(tm0, __shfl_xor_sync(0xffffffffu, tm0, 2));
        tm1 = fmaxf(tm1, __shfl_xor_sync(0xffffffffu, tm1, 1));
        tm1 = fmaxf(tm1, __shfl_xor_sync(0xffffffffu, tm1, 2));
        float mn0 = fmaxf(m0, tm0), mn1 = fmaxf(m1, tm1);
        float al0 = __expf(m0 - mn0), al1 = __expf(m1 - mn1);
        m0 = mn0; m1 = mn1;

        float rs0 = 0.f, rs1 = 0.f;
        uint32_t ph[4][4], pl[4][4];
        #pragma unroll
        for (int nb = 0; nb < 8; ++nb) {
            float p0 = __expf(sacc[nb][0] - mn0);
            float p1 = __expf(sacc[nb][1] - mn0);
            float p2 = __expf(sacc[nb][2] - mn1);
            float p3 = __expf(sacc[nb][3] - mn1);
            rs0 += p0 + p1; rs1 += p2 + p3;
            __nv_bfloat16 h0,h1,h2,h3,lo0,lo1,lo2,lo3;
            split_bf(p0, h0, lo0); split_bf(p1, h1, lo1);
            split_bf(p2, h2, lo2); split_bf(p3, h3, lo3);
            const int ks = nb >> 1;
            const int rb = (nb & 1) * 2;
            ph[ks][rb+0] = pack_bf(h0, h1);
            ph[ks][rb+1] = pack_bf(h2, h3);
            pl[ks][rb+0] = pack_bf(lo0, lo1);
            pl[ks][rb+1] = pack_bf(lo2, lo3);
        }
        rs0 += __shfl_xor_sync(0xffffffffu, rs0, 1);
        rs0 += __shfl_xor_sync(0xffffffffu, rs0, 2);
        rs1 += __shfl_xor_sync(0xffffffffu, rs1, 1);
        rs1 += __shfl_xor_sync(0xffffffffu, rs1, 2);
        l0 = l0*al0 + rs0;
        l1 = l1*al1 + rs1;
        #pragma unroll
        for (int nb = 0; nb < 8; ++nb) {
            oacc[nb][0] *= al0; oacc[nb][1] *= al0;
            oacc[nb][2] *= al1; oacc[nb][3] *= al1;
        }

        // ---- PV: O += P V (bf16x3) ----
        #pragma unroll
        for (int ks = 0; ks < 4; ++ks) {
            uint32_t vh2[8][2], vl2[8][2];
            #pragma unroll
            for (int np = 0; np < 4; ++np) {
                uint32_t so = swz128(ks*16 + b_r, np*2 + lu);
                uint32_t t0, t1, t2, t3;
                ldsm4t(t0, t1, t2, t3, st + 16384u + so);
                vh2[np*2][0] = t0; vh2[np*2][1] = t1;
                vh2[np*2+1][0] = t2; vh2[np*2+1][1] = t3;
                ldsm4t(t0, t1, t2, t3, st + 24576u + so);
                vl2[np*2][0] = t0; vl2[np*2][1] = t1;
                vl2[np*2+1][0] = t2; vl2[np*2+1][1] = t3;
            }
            #pragma unroll
            for (int nb = 0; nb < 8; ++nb) {
                mma16816(oacc[nb], ph[ks], vh2[nb]);
                mma16816(oacc[nb], pl[ks], vh2[nb]);
                mma16816(oacc[nb], ph[ks], vl2[nb]);
            }
        }
        __syncthreads();
    }

    // epilogue: normalize and write z (bf16 hi/lo) at [b][s][h*64+e]
    const float inv0 = 1.0f / l0, inv1 = 1.0f / l1;
    const int b = bh >> 4, h = bh & 15;
    const int r0 = s0 + w*16 + (lane >> 2);
    #pragma unroll
    for (int nb = 0; nb < 8; ++nb) {
        const int c = h*64 + nb*8 + (lane & 3)*2;
        float z0 = oacc[nb][0]*inv0, z1 = oacc[nb][1]*inv0;
        float z2 = oacc[nb][2]*inv1, z3 = oacc[nb][3]*inv1;
        __nv_bfloat16 h0,h1,lo0,lo1;
        size_t o0 = ((size_t)b*SEQ + r0)*DMODEL + c;
        split_bf(z0, h0, lo0); split_bf(z1, h1, lo1);
        *(uint32_t*)&g_z_hi[o0] = pack_bf(h0, h1);
        *(uint32_t*)&g_z_lo[o0] = pack_bf(lo0, lo1);
        split_bf(z2, h0, lo0); split_bf(z3, h1, lo1);
        *(uint32_t*)&g_z_hi[o0 + 8*DMODEL] = pack_bf(h0, h1);
        *(uint32_t*)&g_z_lo[o0 + 8*DMODEL] = pack_bf(lo0, lo1);
    }
}

// ---------------------------------------------------------------------------
extern "C" void kernel_launch(void* const* d_in, const int* in_sizes, int n_in,
                              void* d_out, int out_size) {
    const float* x  = (const float*)d_in[0];
    const float* Wq = (const float*)d_in[1];
    const float* bq = (const float*)d_in[2];
    const float* Wk = (const float*)d_in[3];
    const float* bk = (const float*)d_in[4];
    const float* Wv = (const float*)d_in[5];
    const float* bv = (const float*)d_in[6];
    const float* Wo = (const float*)d_in[7];
    const float* bo = (const float*)d_in[8];
    float* out = (float*)d_out;

    cudaFuncSetAttribute(attn_mma_kernel,
                         cudaFuncAttributeMaxDynamicSharedMemorySize, ATTN_SMEM);
    cudaFuncSetAttribute(mma_gemm_kernel<0>,
                         cudaFuncAttributeMaxDynamicSharedMemorySize, GEMM_SMEM);
    cudaFuncSetAttribute(mma_gemm_kernel<1>,
                         cudaFuncAttributeMaxDynamicSharedMemorySize, GEMM_SMEM);

    // preprocessing
    convert_x_kernel<<<(MTOT*DMODEL)/1024, 256>>>(x);
    repack_wqkv_kernel<<<dim3(16, 48), 256>>>(Wq, Wk, Wv);
    repack_wo_kernel<<<dim3(16, 16), 256>>>(Wo);
    bias_kernel<<<12, 256>>>(bq, bk, bv);

    // QKV projection -> bf16 hi/lo q(scaled),k,v
    mma_gemm_kernel<0><<<dim3(24, 64), 256, GEMM_SMEM>>>(nullptr, nullptr);

    // flash attention (tensor core) -> g_z hi/lo
    attn_mma_kernel<<<dim3(SEQ/BQ, BATCH*NH), 256, ATTN_SMEM>>>();

    // output projection -> out
    mma_gemm_kernel<1><<<dim3(8, 64), 256, GEMM_SMEM>>>(bo, out);
}